// round 3
// baseline (speedup 1.0000x reference)
#include <cuda_runtime.h>

#define DD 512
#define NN 128
#define TPB 256
#define TINYF 1e-30f

// ---- packed f32x2 helpers (Blackwell FFMA2) ----
__device__ __forceinline__ unsigned long long fma2(unsigned long long a,
                                                   unsigned long long b,
                                                   unsigned long long c) {
    unsigned long long d;
    asm("fma.rn.f32x2 %0, %1, %2, %3;" : "=l"(d) : "l"(a), "l"(b), "l"(c));
    return d;
}
__device__ __forceinline__ float lo2(unsigned long long v) {
    return __uint_as_float((unsigned)v);
}
__device__ __forceinline__ float hi2(unsigned long long v) {
    return __uint_as_float((unsigned)(v >> 32));
}
__device__ __forceinline__ unsigned long long pack2(float x, float y) {
    unsigned long long d;
    asm("mov.b64 %0, {%1, %2};" : "=l"(d) : "f"(x), "f"(y));
    return d;
}

// Woodbury-reduced ordered Slater-determinant sampler, single-barrier variant.
//
// State: Rb = R[:, 0:N], R = (I_m - U^T U)^{-1}. Thread r holds row r of Rb
// as 64 packed f32x2 registers. Initial Rb = [I; 0] => q_0 = [P_row0; 0].
//
// Per step i (ONE __syncthreads):
//   all threads: reduce s_i = 1 - up_i . q_i[0:128]  (redundant per warp,
//                bitwise-identical), run the occupy decision redundantly
//                (ratio/cumul/k kept per-thread), thread 0 writes outputs
//   fused pass:  rb2[j] += (q_r*pivinv) * q2[j];  acc += rb2[j] * up_{i+1}[j]
//                (rank-1 of step i + matvec of step i+1 in one register sweep)
//   prefetch:    warps 4-7 stage P row i+2 into the 3-deep sh_up ring
//   barrier
__global__ __launch_bounds__(TPB, 1)
void slater_sampler_kernel(const float* __restrict__ P,
                           const float* __restrict__ uin,
                           float* __restrict__ out,
                           int out_size)
{
    __shared__ __align__(16) float sh_up[3][NN];
    __shared__ __align__(16) float sh_q[2][NN];
    __shared__ __align__(16) float sh_u[NN];

    const int tid  = threadIdx.x;
    const int lane = tid & 31;
    const int pos_base = NN * DD;

    // ---- init output: cond_probs = 0, positions = -1 ----
    {
        int n4 = out_size >> 2;
        float4* o4 = (float4*)out;
        for (int idx = tid; idx < n4; idx += TPB) {
            int base = idx * 4;
            float4 v;
            v.x = (base + 0 < pos_base) ? 0.0f : -1.0f;
            v.y = (base + 1 < pos_base) ? 0.0f : -1.0f;
            v.z = (base + 2 < pos_base) ? 0.0f : -1.0f;
            v.w = (base + 3 < pos_base) ? 0.0f : -1.0f;
            o4[idx] = v;
        }
        for (int idx = (n4 << 2) + tid; idx < out_size; idx += TPB)
            out[idx] = (idx < pos_base) ? 0.0f : -1.0f;
    }

    float qr = 0.0f;
    if (tid < NN) {
        sh_u[tid]     = uin[tid];
        float p0      = P[tid];            // P row 0
        sh_up[0][tid] = p0;
        sh_up[1][tid] = P[NN + tid];       // P row 1
        sh_q[0][tid]  = p0;                // q_0 = [up_0; 0]
        qr            = p0;
    }

    // Rb row in 64 packed f32x2 registers. Identity on top 128 rows.
    unsigned long long rb2[NN / 2];
#pragma unroll
    for (int j = 0; j < NN / 2; ++j) {
        unsigned long long v = 0ULL;
        if ((tid >> 1) == j)
            v = (tid & 1) ? 0x3f80000000000000ULL : 0x000000003f800000ULL;
        rb2[j] = v;
    }

    __syncthreads();

    const bool write_pos = (pos_base + NN) <= out_size;

    // redundant per-thread sampler state (identical across all threads)
    float ratio = 1.0f, cumul = 0.0f;
    int   k = 0;

    for (int i = 0; i < DD; ++i) {
        const int b  = i & 1;
        const int s3 = i % 3;

        // ---- redundant reduction: red = up_i . q_i[0:128] (every warp) ----
        float red;
        {
            const float4* q4 = reinterpret_cast<const float4*>(sh_q[b]);
            const float4* u4 = reinterpret_cast<const float4*>(sh_up[s3]);
            float4 qv = q4[lane];
            float4 uv = u4[lane];
            red = (qv.x * uv.x + qv.y * uv.y) + (qv.z * uv.z + qv.w * uv.w);
#pragma unroll
            for (int o = 16; o; o >>= 1)
                red += __shfl_xor_sync(0xffffffffu, red, o);
        }

        // ---- redundant decision (identical on all threads) ----
        float s = 1.0f - red;
        int last_allowed = DD - NN + k;
        float p  = -(s - 1.0f) * ratio;
        float uk = sh_u[k];
        bool occupy = ((cumul + p) >= uk) || (i == last_allowed);

        float pivot = occupy ? (s - 1.0f) : s;
        if (fabsf(pivot) < TINYF) pivot = TINYF;
        float pivinv = 1.0f / pivot;

        if (tid == 0) {
            out[k * DD + i] = p;
            if (occupy && write_pos) out[pos_base + k] = (float)i;
        }

        int newrow = occupy ? (NN + k) : -1;
        if (occupy) { ratio = 1.0f; cumul = 0.0f; ++k; }
        else        { ratio *= s;  cumul += p; }

        if (k == NN) break;   // final occupation done; Rb never queried again

        // ---- fused: rank-1(i) + matvec(i+1) in one register sweep ----
        float nqr = 0.0f;
        const bool act = (tid < NN + k);   // includes freshly activated row
        if (act) {
            float myq = (tid == newrow) ? 1.0f : qr;
            float scale = myq * pivinv;
            unsigned long long s2 = pack2(scale, scale);
            const ulonglong2* q2  = reinterpret_cast<const ulonglong2*>(sh_q[b]);
            const ulonglong2* un2 = reinterpret_cast<const ulonglong2*>(sh_up[(i + 1) % 3]);
            unsigned long long a0 = 0, a1 = 0, a2 = 0, a3 = 0;
#pragma unroll
            for (int j = 0; j < 16; ++j) {
                ulonglong2 qa = q2[2 * j];
                ulonglong2 qb = q2[2 * j + 1];
                ulonglong2 ua = un2[2 * j];
                ulonglong2 ub = un2[2 * j + 1];
                rb2[4 * j + 0] = fma2(s2, qa.x, rb2[4 * j + 0]);
                rb2[4 * j + 1] = fma2(s2, qa.y, rb2[4 * j + 1]);
                rb2[4 * j + 2] = fma2(s2, qb.x, rb2[4 * j + 2]);
                rb2[4 * j + 3] = fma2(s2, qb.y, rb2[4 * j + 3]);
                a0 = fma2(rb2[4 * j + 0], ua.x, a0);
                a1 = fma2(rb2[4 * j + 1], ua.y, a1);
                a2 = fma2(rb2[4 * j + 2], ub.x, a2);
                a3 = fma2(rb2[4 * j + 3], ub.y, a3);
            }
            nqr = ((lo2(a0) + hi2(a0)) + (lo2(a1) + hi2(a1)))
                + ((lo2(a2) + hi2(a2)) + (lo2(a3) + hi2(a3)));
            if (tid < NN) sh_q[b ^ 1][tid] = nqr;
        }
        qr = nqr;

        // ---- prefetch P row i+2 (warps 4-7, off critical path) ----
        if (tid >= NN && i + 2 < DD)
            sh_up[(i + 2) % 3][tid - NN] = P[(size_t)(i + 2) * NN + (tid - NN)];

        __syncthreads();   // the ONLY barrier per step
    }
}

extern "C" void kernel_launch(void* const* d_in, const int* in_sizes, int n_in,
                              void* d_out, int out_size)
{
    const float* P = (const float*)d_in[0];   // (512, 128) row-major
    const float* u = (const float*)d_in[1];   // (128,)
    float* out = (float*)d_out;
    slater_sampler_kernel<<<1, TPB>>>(P, u, out, out_size);
}

// round 4
// speedup vs baseline: 1.1437x; 1.1437x over previous
#include <cuda_runtime.h>

#define DD 512
#define NN 128
#define TPB 512
#define TINYF 1e-30f

// ---- packed f32x2 helpers (Blackwell FFMA2) ----
__device__ __forceinline__ unsigned long long fma2(unsigned long long a,
                                                   unsigned long long b,
                                                   unsigned long long c) {
    unsigned long long d;
    asm("fma.rn.f32x2 %0, %1, %2, %3;" : "=l"(d) : "l"(a), "l"(b), "l"(c));
    return d;
}
__device__ __forceinline__ float lo2(unsigned long long v) {
    return __uint_as_float((unsigned)v);
}
__device__ __forceinline__ float hi2(unsigned long long v) {
    return __uint_as_float((unsigned)(v >> 32));
}
__device__ __forceinline__ unsigned long long pack2(float x, float y) {
    unsigned long long d;
    asm("mov.b64 %0, {%1, %2};" : "=l"(d) : "f"(x), "f"(y));
    return d;
}

// Woodbury-reduced ordered Slater-determinant sampler, top-block-only.
//
// Key fact (dataflow-verified on the previous passing kernel): the occupation
// rows (128..255) of the Woodbury inverse never influence the output — the
// occupy decision enters the top 128x128 block ONLY through the pivot value
// (s-1 vs s). So the state is just Rb (128x128), rank-1 updated each step.
//
// Layout: 512 threads; thread t owns row r = t&127, column slice
// [32h, 32h+32) with h = t>>7, held as 16 packed f32x2 registers.
//
// Per step i (2 barriers):
//   phase A: q_i[r] = 4-way sum of sh_part; redundant per-warp reduction of
//            red = up_i . q_i; redundant decision (ratio/cumul/k per-thread);
//            tid<128 stage sh_q, STS prefetched P row, issue next LDG.
//   B_mid
//   phase B: fused rank-1 (rb += (q_r pivinv) q-slice) + next matvec partial
//            (acc += rb * up_{i+1}-slice); write sh_part.
//   B_end
__global__ __launch_bounds__(TPB, 1)
void slater_sampler_kernel(const float* __restrict__ P,
                           const float* __restrict__ uin,
                           float* __restrict__ out,
                           int out_size)
{
    __shared__ __align__(16) float sh_up[3][NN];
    __shared__ __align__(16) float sh_q[NN];
    __shared__ __align__(16) float sh_part[TPB];
    __shared__ __align__(16) float sh_u[NN];

    const int tid  = threadIdx.x;
    const int lane = tid & 31;
    const int r    = tid & 127;
    const int h    = tid >> 7;          // 0..3
    const int cbase = 32 * h;           // this thread's column base
    const int pos_base = NN * DD;

    // ---- init output: cond_probs = 0, positions = -1 ----
    {
        int n4 = out_size >> 2;
        float4* o4 = (float4*)out;
        for (int idx = tid; idx < n4; idx += TPB) {
            int base = idx * 4;
            float4 v;
            v.x = (base + 0 < pos_base) ? 0.0f : -1.0f;
            v.y = (base + 1 < pos_base) ? 0.0f : -1.0f;
            v.z = (base + 2 < pos_base) ? 0.0f : -1.0f;
            v.w = (base + 3 < pos_base) ? 0.0f : -1.0f;
            o4[idx] = v;
        }
        for (int idx = (n4 << 2) + tid; idx < out_size; idx += TPB)
            out[idx] = (idx < pos_base) ? 0.0f : -1.0f;
    }

    float pfreg = 0.0f;
    if (tid < NN) {
        sh_u[tid]     = uin[tid];
        sh_up[0][tid] = P[tid];               // row 0
        pfreg         = P[NN + tid];          // row 1 (STS'd at i=0)
    }

    // Initial partials for q_0 = Rb*up_0 = up_0 (Rb = I):
    // thread contributes up0[r] iff r falls in its column slice.
    sh_part[tid] = (r >= cbase && r < cbase + 32) ? P[r] : 0.0f;

    // Rb slice: identity.
    unsigned long long rb2[16];
#pragma unroll
    for (int m = 0; m < 16; ++m) {
        unsigned long long v = 0ULL;
        int c0 = cbase + 2 * m;               // columns (c0, c0+1)
        if (c0 == r)      v = 0x000000003f800000ULL;
        else if (c0 + 1 == r) v = 0x3f80000000000000ULL;
        rb2[m] = v;
    }

    __syncthreads();

    const bool write_pos = (pos_base + NN) <= out_size;

    // redundant per-thread sampler state (identical across all threads)
    float ratio = 1.0f, cumul = 0.0f;
    int   k = 0;

    for (int i = 0; i < DD; ++i) {
        const float* up = sh_up[i % 3];

        // ---- redundant reduction: red = up_i . q_i  (every warp, identical) ----
        float red;
        {
            const float4* u4 = reinterpret_cast<const float4*>(up);
            const float4* p4 = reinterpret_cast<const float4*>(sh_part);
            float4 a = p4[lane];
            float4 b = p4[lane + 32];
            float4 c = p4[lane + 64];
            float4 d = p4[lane + 96];
            float4 uv = u4[lane];
            float qx = (a.x + b.x) + (c.x + d.x);
            float qy = (a.y + b.y) + (c.y + d.y);
            float qz = (a.z + b.z) + (c.z + d.z);
            float qw = (a.w + b.w) + (c.w + d.w);
            red = (uv.x * qx + uv.y * qy) + (uv.z * qz + uv.w * qw);
#pragma unroll
            for (int o = 16; o; o >>= 1)
                red += __shfl_xor_sync(0xffffffffu, red, o);
        }

        // ---- per-thread q_r; tid<128 stage sh_q ----
        float qr = (sh_part[r] + sh_part[r + 128])
                 + (sh_part[r + 256] + sh_part[r + 384]);
        if (tid < NN) sh_q[tid] = qr;

        // ---- software-pipelined P prefetch (tid<128) ----
        if (tid < NN) {
            if (i + 1 < DD) sh_up[(i + 1) % 3][tid] = pfreg;
            if (i + 2 < DD) pfreg = P[(size_t)(i + 2) * NN + tid];
        }

        // ---- redundant decision ----
        float s = 1.0f - red;
        int last_allowed = DD - NN + k;
        float p  = -(s - 1.0f) * ratio;
        float uk = sh_u[k];
        bool occupy = ((cumul + p) >= uk) || (i == last_allowed);

        float pivot = occupy ? (s - 1.0f) : s;
        if (fabsf(pivot) < TINYF) pivot = TINYF;
        float pivinv = 1.0f / pivot;

        if (tid == 0) {
            out[k * DD + i] = p;
            if (occupy && write_pos) out[pos_base + k] = (float)i;
        }
        if (occupy) { ratio = 1.0f; cumul = 0.0f; ++k; }
        else        { ratio *= s;  cumul += p; }

        __syncthreads();   // B_mid: sh_q + next up visible

        if (k == NN) break;   // final occupation done (always hits by i=DD-1)

        // ---- fused: rank-1(i) on rb slice + matvec(i+1) partial ----
        float scale = qr * pivinv;
        unsigned long long s2 = pack2(scale, scale);
        const ulonglong2* q2 = reinterpret_cast<const ulonglong2*>(sh_q + cbase);
        const ulonglong2* u2 = reinterpret_cast<const ulonglong2*>(sh_up[(i + 1) % 3] + cbase);
        unsigned long long a0 = 0, a1 = 0, a2 = 0, a3 = 0;
#pragma unroll
        for (int j = 0; j < 4; ++j) {
            ulonglong2 qa = q2[2 * j];
            ulonglong2 qb = q2[2 * j + 1];
            ulonglong2 ua = u2[2 * j];
            ulonglong2 ub = u2[2 * j + 1];
            rb2[4 * j + 0] = fma2(s2, qa.x, rb2[4 * j + 0]);
            a0 = fma2(rb2[4 * j + 0], ua.x, a0);
            rb2[4 * j + 1] = fma2(s2, qa.y, rb2[4 * j + 1]);
            a1 = fma2(rb2[4 * j + 1], ua.y, a1);
            rb2[4 * j + 2] = fma2(s2, qb.x, rb2[4 * j + 2]);
            a2 = fma2(rb2[4 * j + 2], ub.x, a2);
            rb2[4 * j + 3] = fma2(s2, qb.y, rb2[4 * j + 3]);
            a3 = fma2(rb2[4 * j + 3], ub.y, a3);
        }
        sh_part[tid] = ((lo2(a0) + hi2(a0)) + (lo2(a1) + hi2(a1)))
                     + ((lo2(a2) + hi2(a2)) + (lo2(a3) + hi2(a3)));

        __syncthreads();   // B_end: partials visible
    }
}

extern "C" void kernel_launch(void* const* d_in, const int* in_sizes, int n_in,
                              void* d_out, int out_size)
{
    const float* P = (const float*)d_in[0];   // (512, 128) row-major
    const float* u = (const float*)d_in[1];   // (128,)
    float* out = (float*)d_out;
    slater_sampler_kernel<<<1, TPB>>>(P, u, out, out_size);
}